// round 17
// baseline (speedup 1.0000x reference)
#include <cuda_runtime.h>
#include <math.h>
#include <stdint.h>

#define LAYERS 4
#define S 2048
#define D 1024
#define HQ 16
#define KVH 4
#define HD 64
#define II 4096
#define VV 32000
#define EPSV 1e-6f

__device__ float g_h[S * D];
__device__ float g_q[S * HQ * HD];
__device__ float g_k[S * KVH * HD];
__device__ float g_v[S * KVH * HD];
__device__ float g_gate[S * II];
__device__ float g_up[S * II];
__device__ float g_cos[S * 32];
__device__ float g_sin[S * 32];
__device__ float g_rms[S];

// split-KV partial scratch (3 splits)
__device__ float g_po[3 * HQ * S * HD];
__device__ float g_pm[3 * HQ * S];
__device__ float g_pl[3 * HQ * S];

// weights in mma-frag layout, hi/lo tf32: [pan][kb][nb(16)][64]
#define OQW  0
#define OKW  1048576
#define OVW  1310720
#define OOW  1572864
#define OGW  2621440
#define OUW  6815744
#define ODW  11010048
#define LSZ  15204352
#define OLM  60817408
#define WTOT 93585408
__device__ uint32_t g_wt_hi[WTOT];
__device__ uint32_t g_wt_lo[WTOT];

// activations in mma-frag layout, hi/lo: [mt][kb][mb(8)][128]
#define AMAX (S * II)
__device__ uint32_t g_a_hi[AMAX];
__device__ uint32_t g_a_lo[AMAX];

__device__ __forceinline__ uint32_t f2tf32(float f) {
    uint32_t u; asm("cvt.rna.tf32.f32 %0, %1;" : "=r"(u) : "f"(f)); return u;
}
__device__ __forceinline__ uint32_t smem_u32(const void* p) {
    uint32_t a;
    asm("{ .reg .u64 t; cvta.to.shared.u64 t, %1; cvt.u32.u64 %0, t; }" : "=r"(a) : "l"(p));
    return a;
}
__device__ __forceinline__ void cp_async16(uint32_t dst, const void* src) {
    asm volatile("cp.async.cg.shared.global [%0], [%1], 16;" :: "r"(dst), "l"(src) : "memory");
}
__device__ __forceinline__ void cp_commit() {
    asm volatile("cp.async.commit_group;" ::: "memory");
}
template <int N>
__device__ __forceinline__ void cp_wait() {
    asm volatile("cp.async.wait_group %0;" :: "n"(N) : "memory");
}

#define MMA_TF32(c, a, b)                                                     \
    asm volatile(                                                             \
        "mma.sync.aligned.m16n8k8.row.col.f32.tf32.tf32.f32 "                 \
        "{%0,%1,%2,%3},{%4,%5,%6,%7},{%8,%9},{%0,%1,%2,%3};"                  \
        : "+f"(c[0]), "+f"(c[1]), "+f"(c[2]), "+f"(c[3])                      \
        : "r"(a.x), "r"(a.y), "r"(a.z), "r"(a.w), "r"(b.x), "r"(b.y))

// ---------------- misc kernels ------------------------------------------------
__global__ void rope_table_kernel() {
    int idx = blockIdx.x * blockDim.x + threadIdx.x;
    if (idx >= S * 32) return;
    int s = idx >> 5, i = idx & 31;
    double invf = exp(-((double)(2 * i) / (double)HD) * log(10000.0));
    float af = (float)s * (float)invf;
    g_cos[idx] = (float)cos((double)af);
    g_sin[idx] = (float)sin((double)af);
}

__global__ void embed_kernel(const float* __restrict__ embed, const int* __restrict__ ids) {
    int idx = blockIdx.x * blockDim.x + threadIdx.x;
    int s = idx / (D / 4), c = idx % (D / 4);
    ((float4*)(g_h + (size_t)s * D))[c] = ((const float4*)(embed + (size_t)ids[s] * D))[c];
}

__global__ void rms_scale_kernel(const float* __restrict__ X) {
    int row = blockIdx.x;
    const float* x = X + (size_t)row * D;
    float ss = 0.f;
    for (int i = threadIdx.x; i < D; i += blockDim.x) { float v = x[i]; ss = fmaf(v, v, ss); }
    __shared__ float sred[32];
    #pragma unroll
    for (int off = 16; off; off >>= 1) ss += __shfl_xor_sync(0xffffffffu, ss, off);
    int wid = threadIdx.x >> 5, lid = threadIdx.x & 31;
    if (lid == 0) sred[wid] = ss;
    __syncthreads();
    if (wid == 0) {
        ss = (lid < (int)(blockDim.x >> 5)) ? sred[lid] : 0.f;
        #pragma unroll
        for (int off = 16; off; off >>= 1) ss += __shfl_xor_sync(0xffffffffu, ss, off);
        if (lid == 0) g_rms[row] = rsqrtf(ss / (float)D + EPSV);
    }
}

__global__ void rope_kernel(float* __restrict__ X, int nheads) {
    int idx = blockIdx.x * blockDim.x + threadIdx.x;
    if (idx >= S * nheads * 32) return;
    int i = idx & 31, h = (idx >> 5) % nheads, s = idx / (32 * nheads);
    float c = g_cos[s * 32 + i], sn = g_sin[s * 32 + i];
    float* p = X + (size_t)s * nheads * HD + h * HD;
    float x1 = p[i], x2 = p[i + 32];
    p[i] = x1 * c - x2 * sn;
    p[i + 32] = x2 * c + x1 * sn;
}

// ---------------- weight prep: W[K][N] -> frag layout hi(/lo) -----------------
template <bool WLO>
__global__ void wprep_kernel(const float* __restrict__ W, uint32_t* __restrict__ hi,
                             uint32_t* __restrict__ lo, int K, int N) {
    __shared__ uint32_t sh[1024];
    __shared__ uint32_t sl[1024];
    int pan = blockIdx.x;
    int r = threadIdx.x & 7;
    int n0 = (threadIdx.x >> 3) * 4;
    #pragma unroll
    for (int i = 0; i < 4; i++) {
        int kb = blockIdx.y * 4 + i;
        float4 v = *(const float4*)(W + (size_t)(kb * 8 + r) * N + pan * 128 + n0);
        float f[4] = {v.x, v.y, v.z, v.w};
        #pragma unroll
        for (int j = 0; j < 4; j++) {
            int n = n0 + j;
            int pos = ((n >> 3) << 6) + ((n & 7) << 3) + ((r & 3) << 1) + (r >> 2);
            uint32_t h = f2tf32(f[j]);
            sh[pos] = h;
            if (WLO) sl[pos] = f2tf32(f[j] - __uint_as_float(h));
        }
        __syncthreads();
        size_t base = (size_t)((uint32_t)(pan * (K >> 3) + kb)) * 1024;
        int e = threadIdx.x * 4;
        *(uint4*)(hi + base + e) = *(const uint4*)(sh + e);
        if (WLO) *(uint4*)(lo + base + e) = *(const uint4*)(sl + e);
        __syncthreads();
    }
}

// ---------------- activation prep -----------------------------------------
// MODE 0: plain ; MODE 1: silu(A)*U ; MODE 2: rmsnorm w[col]*A*g_rms[row]
// MODE 3: merge 3 attention partials inline (A/U/w unused)
template <int MODE>
__global__ void asplit_kernel(const float* __restrict__ A, const float* __restrict__ U,
                              const float* __restrict__ w, int K) {
    __shared__ uint32_t sh[1024];
    __shared__ uint32_t sl[1024];
    int mt = blockIdx.x;
    int m = threadIdx.x >> 1;
    int k0 = (threadIdx.x & 1) * 4;
    float rscale = (MODE == 2) ? g_rms[mt * 128 + m] : 0.f;
    #pragma unroll
    for (int i = 0; i < 4; i++) {
        int kb = blockIdx.y * 4 + i;
        float f[4];
        if (MODE == 3) {
            int row = mt * 128 + m;
            int kcol = kb * 8 + k0;
            int hq = kcol >> 6, d4 = kcol & 63;
            size_t rh = (size_t)hq * S + row;
            size_t p0 = rh, p1 = (size_t)(HQ * S) + rh, p2 = (size_t)(2 * HQ * S) + rh;
            float m0 = g_pm[p0], m1 = g_pm[p1], m2 = g_pm[p2];
            float l0 = g_pl[p0], l1 = g_pl[p1], l2 = g_pl[p2];
            float M = fmaxf(fmaxf(m0, m1), m2);
            float s0 = __expf(m0 - M), s1 = __expf(m1 - M), s2 = __expf(m2 - M);
            float inv = 1.f / (l0 * s0 + l1 * s1 + l2 * s2);
            float4 a = *(const float4*)&g_po[p0 * HD + d4];
            float4 b = *(const float4*)&g_po[p1 * HD + d4];
            float4 c = *(const float4*)&g_po[p2 * HD + d4];
            f[0] = (a.x * s0 + b.x * s1 + c.x * s2) * inv;
            f[1] = (a.y * s0 + b.y * s1 + c.y * s2) * inv;
            f[2] = (a.z * s0 + b.z * s1 + c.z * s2) * inv;
            f[3] = (a.w * s0 + b.w * s1 + c.w * s2) * inv;
        } else {
            size_t gofs = (size_t)(mt * 128 + m) * K + kb * 8 + k0;
            float4 v = *(const float4*)(A + gofs);
            f[0] = v.x; f[1] = v.y; f[2] = v.z; f[3] = v.w;
            if (MODE == 1) {
                float4 u = *(const float4*)(U + gofs);
                float uu[4] = {u.x, u.y, u.z, u.w};
                #pragma unroll
                for (int j = 0; j < 4; j++)
                    f[j] = f[j] / (1.f + __expf(-f[j])) * uu[j];
            } else if (MODE == 2) {
                float4 ww = *(const float4*)(w + kb * 8 + k0);
                float wv[4] = {ww.x, ww.y, ww.z, ww.w};
                #pragma unroll
                for (int j = 0; j < 4; j++)
                    f[j] = wv[j] * (f[j] * rscale);
            }
        }
        #pragma unroll
        for (int j = 0; j < 4; j++) {
            int k = k0 + j;
            int lane = ((m & 7) << 2) + (k & 3);
            int reg = ((m >> 3) & 1) + 2 * ((k >> 2) & 1);
            int pos = ((m >> 4) << 7) + lane * 4 + reg;
            uint32_t h = f2tf32(f[j]);
            sh[pos] = h;
            sl[pos] = f2tf32(f[j] - __uint_as_float(h));
        }
        __syncthreads();
        size_t base = (size_t)((uint32_t)(mt * (K >> 3) + kb)) * 1024;
        int e = threadIdx.x * 4;
        *(uint4*)(g_a_hi + base + e) = *(const uint4*)(sh + e);
        *(uint4*)(g_a_lo + base + e) = *(const uint4*)(sl + e);
        __syncthreads();
    }
}

// ---------------- 3x/2x TF32 GEMM, deep cp.async pipeline, split-K ------------
// PASSES=3: 3 stages x 32KB ; PASSES=2: 4 stages x 24KB (no Blo)
struct GemmSeg {
    const uint32_t* Bhi; const uint32_t* Blo;
    const float* bias; float* C; int N; int nx;
};
#define SMEM7 98304

template <int PASSES>
__global__ void __launch_bounds__(256, 2)
mm7_kernel(GemmSeg s0, GemmSeg s1, GemmSeg s2, int K, int mode) {
    extern __shared__ __align__(128) uint32_t sm[];
    constexpr int STAGES = (PASSES == 3) ? 3 : 4;
    constexpr int STRIDE_W = (PASSES == 3) ? 8192 : 6144;   // uint32 words per stage
    constexpr int AHEAD = STAGES - 1;

    int bx = blockIdx.x;
    const uint32_t *Bhi, *Blo;
    const float* bias; float* Cp; int N;
    if (bx < s0.nx) { Bhi = s0.Bhi; Blo = s0.Blo; bias = s0.bias; Cp = s0.C; N = s0.N; }
    else if (bx < s0.nx + s1.nx) { bx -= s0.nx; Bhi = s1.Bhi; Blo = s1.Blo; bias = s1.bias; Cp = s1.C; N = s1.N; }
    else { bx -= s0.nx + s1.nx; Bhi = s2.Bhi; Blo = s2.Blo; bias = s2.bias; Cp = s2.C; N = s2.N; }
    const int pan = bx;
    const int mt = blockIdx.y;

    const int tid = threadIdx.x;
    const int lane = tid & 31;
    const int warp = tid >> 5;
    const int wm = warp & 1;
    const int wn = warp >> 1;

    const uint32_t smb = smem_u32(sm);
    const int KB8 = K >> 3;
    const int KB8z = KB8 / (int)gridDim.z;
    const int kb0 = blockIdx.z * KB8z;

    float acc[4][4][4];
    #pragma unroll
    for (int i = 0; i < 4; i++)
        #pragma unroll
        for (int j = 0; j < 4; j++)
            #pragma unroll
            for (int r = 0; r < 4; r++) acc[i][j][r] = 0.f;

    auto copy_tile = [&](int t, int buf) {
        const uint32_t* srcA_hi = g_a_hi + ((size_t)(mt * KB8 + kb0 + 2 * t)) * 1024;
        const uint32_t* srcA_lo = g_a_lo + ((size_t)(mt * KB8 + kb0 + 2 * t)) * 1024;
        const uint32_t* srcB_hi = Bhi + ((size_t)(pan * KB8 + kb0 + 2 * t)) * 1024;
        const uint32_t* srcB_lo = Blo + ((size_t)(pan * KB8 + kb0 + 2 * t)) * 1024;
        uint32_t dst = smb + buf * (STRIDE_W * 4);
        #pragma unroll
        for (int j = 0; j < 2; j++) {
            int e = (tid + j * 256) * 4;
            cp_async16(dst + e * 4,         srcA_hi + e);
            cp_async16(dst + 8192 + e * 4,  srcA_lo + e);
            cp_async16(dst + 16384 + e * 4, srcB_hi + e);
            if (PASSES == 3)
                cp_async16(dst + 24576 + e * 4, srcB_lo + e);
        }
        cp_commit();
    };

    const int ntiles = KB8z >> 1;
    #pragma unroll
    for (int p = 0; p < AHEAD; p++)
        if (p < ntiles) copy_tile(p, p);

    int buf_idx = 0;
    for (int t = 0; t < ntiles; t++) {
        if (PASSES == 2 && t + 2 < ntiles) cp_wait<2>();
        else if (t + 1 < ntiles) cp_wait<1>();
        else cp_wait<0>();
        __syncthreads();
        if (t + AHEAD < ntiles) {
            int b2 = buf_idx + AHEAD; if (b2 >= STAGES) b2 -= STAGES;
            copy_tile(t + AHEAD, b2);
        }

        const uint32_t* buf = sm + buf_idx * STRIDE_W;
        const uint32_t* Ahi_s = buf;
        const uint32_t* Alo_s = buf + 2048;
        const uint32_t* Bhi_s = buf + 4096;
        const uint32_t* Blo_s = buf + 6144;

        #pragma unroll
        for (int ks = 0; ks < 2; ks++) {
            uint4 af[4];
            uint2 bf[4];
            #pragma unroll
            for (int mf = 0; mf < 4; mf++)
                af[mf] = *(const uint4*)&Ahi_s[((ks * 8) + wm * 4 + mf) * 128 + lane * 4];
            #pragma unroll
            for (int nf = 0; nf < 4; nf++)
                bf[nf] = *(const uint2*)&Bhi_s[((ks * 16) + wn * 4 + nf) * 64 + lane * 2];
            #pragma unroll
            for (int mf = 0; mf < 4; mf++)
                #pragma unroll
                for (int nf = 0; nf < 4; nf++)
                    MMA_TF32(acc[mf][nf], af[mf], bf[nf]);
            if (PASSES == 3) {
                uint2 bl[4];
                #pragma unroll
                for (int nf = 0; nf < 4; nf++)
                    bl[nf] = *(const uint2*)&Blo_s[((ks * 16) + wn * 4 + nf) * 64 + lane * 2];
                #pragma unroll
                for (int mf = 0; mf < 4; mf++)
                    #pragma unroll
                    for (int nf = 0; nf < 4; nf++)
                        MMA_TF32(acc[mf][nf], af[mf], bl[nf]);
            }
            #pragma unroll
            for (int mf = 0; mf < 4; mf++)
                af[mf] = *(const uint4*)&Alo_s[((ks * 8) + wm * 4 + mf) * 128 + lane * 4];
            #pragma unroll
            for (int mf = 0; mf < 4; mf++)
                #pragma unroll
                for (int nf = 0; nf < 4; nf++)
                    MMA_TF32(acc[mf][nf], af[mf], bf[nf]);
        }
        buf_idx++; if (buf_idx == STAGES) buf_idx = 0;
    }

    const int g = lane >> 2, tg = lane & 3;
    const int col0 = pan * 128;
    #pragma unroll
    for (int nf = 0; nf < 4; nf++) {
        int cc = col0 + wn * 32 + nf * 8 + tg * 2;
        float b0 = 0.f, b1 = 0.f;
        if (mode == 0 && bias) { b0 = bias[cc]; b1 = bias[cc + 1]; }
        #pragma unroll
        for (int mf = 0; mf < 4; mf++) {
            int rr = mt * 128 + wm * 64 + mf * 16 + g;
            float* c0 = &Cp[(size_t)rr * N + cc];
            float* c1 = &Cp[(size_t)(rr + 8) * N + cc];
            if (mode == 0) {
                *(float2*)c0 = make_float2(acc[mf][nf][0] + b0, acc[mf][nf][1] + b1);
                *(float2*)c1 = make_float2(acc[mf][nf][2] + b0, acc[mf][nf][3] + b1);
            } else if (mode == 1) {
                float2 o0 = *(float2*)c0, o1 = *(float2*)c1;
                o0.x += acc[mf][nf][0]; o0.y += acc[mf][nf][1];
                o1.x += acc[mf][nf][2]; o1.y += acc[mf][nf][3];
                *(float2*)c0 = o0; *(float2*)c1 = o1;
            } else {
                atomicAdd(c0,     acc[mf][nf][0]);
                atomicAdd(c0 + 1, acc[mf][nf][1]);
                atomicAdd(c1,     acc[mf][nf][2]);
                atomicAdd(c1 + 1, acc[mf][nf][3]);
            }
        }
    }
}

// ---------------- attention, split-KV=3: partial (o, m, l) --------------------
#define AKV 64
__global__ void __launch_bounds__(256)
attn_part_kernel() {
    __shared__ float Ks[AKV][HD];
    __shared__ float Vs[AKV][HD];
    const int bx = blockIdx.x;
    const int hq = blockIdx.y * 2 + (threadIdx.x >> 7);
    const int kvh = hq >> 2;
    const int tid128 = threadIdx.x & 127;
    const int row = bx * 128 + tid128;
    const int z = blockIdx.z;

    const int nt = bx + 1;
    const int t0 = (nt * z) / 3;
    const int t1 = (nt * (z + 1)) / 3;

    float o[HD];
    #pragma unroll
    for (int d = 0; d < HD; d++) o[d] = 0.f;
    float m = -INFINITY, l = 0.f;

    if (t1 > t0) {
        float qr[HD];
        #pragma unroll
        for (int d = 0; d < HD; d += 4) {
            float4 t = *(const float4*)&g_q[(size_t)row * (HQ * HD) + hq * HD + d];
            qr[d] = t.x * 0.125f; qr[d + 1] = t.y * 0.125f;
            qr[d + 2] = t.z * 0.125f; qr[d + 3] = t.w * 0.125f;
        }
        for (int j0 = t0 * 128; j0 < t1 * 128; j0 += AKV) {
            __syncthreads();
            for (int t = threadIdx.x; t < AKV * (HD / 4); t += 256) {
                int r = t / (HD / 4), c = (t % (HD / 4)) * 4;
                size_t g = (size_t)(j0 + r) * (KVH * HD) + kvh * HD + c;
                *(float4*)&Ks[r][c] = *(const float4*)&g_k[g];
                *(float4*)&Vs[r][c] = *(const float4*)&g_v[g];
            }
            __syncthreads();
            int jmax = row + 1 - j0;
            if (jmax > AKV) jmax = AKV;
            for (int j = 0; j < jmax; j++) {
                float s0 = 0.f, s1 = 0.f, s2 = 0.f, s3 = 0.f;
                #pragma unroll
                for (int d = 0; d < HD; d += 4) {
                    float4 k4 = *(const float4*)&Ks[j][d];
                    s0 = fmaf(qr[d], k4.x, s0);
                    s1 = fmaf(qr[d + 1], k4.y, s1);
                    s2 = fmaf(qr[d + 2], k4.z, s2);
                    s3 = fmaf(qr[d + 3], k4.w, s3);
                }
                float s = (s0 + s1) + (s2 + s3);
                if (s > m) {
                    float corr = __expf(m - s);
                    l *= corr;
                    #pragma unroll
                    for (int d = 0; d < HD; d++) o[d] *= corr;
                    m = s;
                }
                float p = __expf(s - m);
                l += p;
                #pragma unroll
                for (int d = 0; d < HD; d += 4) {
                    float4 vv = *(const float4*)&Vs[j][d];
                    o[d] = fmaf(p, vv.x, o[d]);
                    o[d + 1] = fmaf(p, vv.y, o[d + 1]);
                    o[d + 2] = fmaf(p, vv.z, o[d + 2]);
                    o[d + 3] = fmaf(p, vv.w, o[d + 3]);
                }
            }
        }
    }

    size_t pb = ((size_t)(z * HQ + hq) * S + row);
    g_pm[pb] = m;
    g_pl[pb] = l;
    #pragma unroll
    for (int d = 0; d < HD; d += 4)
        *(float4*)&g_po[pb * HD + d] = make_float4(o[d], o[d + 1], o[d + 2], o[d + 3]);
}

// ---------------- host side ---------------------------------------------------
static GemmSeg mkseg(const uint32_t* bh, const uint32_t* bl, const float* bias,
                     float* C, int N, int nx) {
    GemmSeg s; s.Bhi = bh; s.Blo = bl; s.bias = bias; s.C = C; s.N = N; s.nx = nx; return s;
}

extern "C" void kernel_launch(void* const* d_in, const int* in_sizes, int n_in,
                              void* d_out, int out_size) {
    const float* embed  = (const float*)d_in[0];
    const float* ln1    = (const float*)d_in[1];
    const float* qw     = (const float*)d_in[2];
    const float* qb     = (const float*)d_in[3];
    const float* kw     = (const float*)d_in[4];
    const float* kb     = (const float*)d_in[5];
    const float* vw     = (const float*)d_in[6];
    const float* vb     = (const float*)d_in[7];
    const float* ow     = (const float*)d_in[8];
    const float* ln2    = (const float*)d_in[9];
    const float* gw     = (const float*)d_in[10];
    const float* uw     = (const float*)d_in[11];
    const float* dw     = (const float*)d_in[12];
    const float* norm_w = (const float*)d_in[13];
    const float* lm_w   = (const float*)d_in[14];
    const int*   ids    = (const int*)d_in[15];
    float* out = (float*)d_out;

    float *p_h, *p_q, *p_k, *p_v, *p_gate, *p_up;
    uint32_t *p_whi, *p_wlo;
    cudaGetSymbolAddress((void**)&p_h, g_h);
    cudaGetSymbolAddress((void**)&p_q, g_q);
    cudaGetSymbolAddress((void**)&p_k, g_k);
    cudaGetSymbolAddress((void**)&p_v, g_v);
    cudaGetSymbolAddress((void**)&p_gate, g_gate);
    cudaGetSymbolAddress((void**)&p_up, g_up);
    cudaGetSymbolAddress((void**)&p_whi, g_wt_hi);
    cudaGetSymbolAddress((void**)&p_wlo, g_wt_lo);

    static bool attr_done = false;
    if (!attr_done) {
        cudaFuncSetAttribute(mm7_kernel<3>, cudaFuncAttributeMaxDynamicSharedMemorySize, SMEM7);
        cudaFuncSetAttribute(mm7_kernel<2>, cudaFuncAttributeMaxDynamicSharedMemorySize, SMEM7);
        attr_done = true;
    }

    // weight prep; ow/gw/uw/lm consumed by 2-pass GEMMs -> skip lo writes
    for (int l = 0; l < LAYERS; l++) {
        size_t lo = (size_t)l * LSZ;
        wprep_kernel<true><<<dim3(8, 32), 256>>>(qw + (size_t)l * 1048576, p_whi + lo + OQW, p_wlo + lo + OQW, 1024, 1024);
        wprep_kernel<true><<<dim3(2, 32), 256>>>(kw + (size_t)l * 262144, p_whi + lo + OKW, p_wlo + lo + OKW, 1024, 256);
        wprep_kernel<true><<<dim3(2, 32), 256>>>(vw + (size_t)l * 262144, p_whi + lo + OVW, p_wlo + lo + OVW, 1024, 256);
        wprep_kernel<false><<<dim3(8, 32), 256>>>(ow + (size_t)l * 1048576, p_whi + lo + OOW, p_wlo + lo + OOW, 1024, 1024);
        wprep_kernel<false><<<dim3(32, 32), 256>>>(gw + (size_t)l * 4194304, p_whi + lo + OGW, p_wlo + lo + OGW, 1024, 4096);
        wprep_kernel<false><<<dim3(32, 32), 256>>>(uw + (size_t)l * 4194304, p_whi + lo + OUW, p_wlo + lo + OUW, 1024, 4096);
        wprep_kernel<true><<<dim3(8, 128), 256>>>(dw + (size_t)l * 4194304, p_whi + lo + ODW, p_wlo + lo + ODW, 4096, 1024);
    }
    wprep_kernel<false><<<dim3(250, 32), 256>>>(lm_w, p_whi + OLM, p_wlo + OLM, 1024, 32000);

    GemmSeg z = mkseg(nullptr, nullptr, nullptr, nullptr, 0, 0);

    rope_table_kernel<<<(S * 32 + 255) / 256, 256>>>();
    embed_kernel<<<(S * D / 4) / 256, 256>>>(embed, ids);

    for (int l = 0; l < LAYERS; l++) {
        size_t lo = (size_t)l * LSZ;
        rms_scale_kernel<<<S, 256>>>(p_h);
        asplit_kernel<2><<<dim3(16, 32), 256>>>(p_h, nullptr, ln1 + (size_t)l * D, 1024);
        {
            GemmSeg sq = mkseg(p_whi + lo + OQW, p_wlo + lo + OQW, qb + (size_t)l * HQ * HD, p_q, HQ * HD, 8);
            GemmSeg sk = mkseg(p_whi + lo + OKW, p_wlo + lo + OKW, kb + (size_t)l * KVH * HD, p_k, KVH * HD, 2);
            GemmSeg sv = mkseg(p_whi + lo + OVW, p_wlo + lo + OVW, vb + (size_t)l * KVH * HD, p_v, KVH * HD, 2);
            mm7_kernel<3><<<dim3(12, 16, 1), 256, SMEM7>>>(sq, sk, sv, D, 0);
        }
        rope_kernel<<<(S * HQ * 32) / 256, 256>>>(p_q, HQ);
        rope_kernel<<<(S * KVH * 32) / 256, 256>>>(p_k, KVH);
        attn_part_kernel<<<dim3(S / 128, HQ / 2, 3), 256>>>();
        // merge fused into asplit MODE 3 (reads partials directly)
        asplit_kernel<3><<<dim3(16, 32), 256>>>(nullptr, nullptr, nullptr, 1024);
        {
            GemmSeg so = mkseg(p_whi + lo + OOW, p_wlo + lo + OOW, nullptr, p_h, D, 8);
            mm7_kernel<2><<<dim3(8, 16, 2), 256, SMEM7>>>(so, z, z, HQ * HD, 2);
        }
        rms_scale_kernel<<<S, 256>>>(p_h);
        asplit_kernel<2><<<dim3(16, 32), 256>>>(p_h, nullptr, ln2 + (size_t)l * D, 1024);
        {
            GemmSeg sg = mkseg(p_whi + lo + OGW, p_wlo + lo + OGW, nullptr, p_gate, II, 32);
            GemmSeg su = mkseg(p_whi + lo + OUW, p_wlo + lo + OUW, nullptr, p_up, II, 32);
            mm7_kernel<2><<<dim3(64, 16, 1), 256, SMEM7>>>(sg, su, z, D, 0);
        }
        asplit_kernel<1><<<dim3(16, 128), 256>>>(p_gate, p_up, nullptr, 4096);
        {
            GemmSeg sd = mkseg(p_whi + lo + ODW, p_wlo + lo + ODW, nullptr, p_h, D, 8);
            mm7_kernel<3><<<dim3(8, 16, 2), 256, SMEM7>>>(sd, z, z, II, 2);
        }
    }

    rms_scale_kernel<<<S, 256>>>(p_h);
    asplit_kernel<2><<<dim3(16, 32), 256>>>(p_h, nullptr, norm_w, 1024);
    {
        GemmSeg sl = mkseg(p_whi + OLM, p_wlo + OLM, nullptr, out, VV, 250);
        mm7_kernel<2><<<dim3(250, 16, 1), 256, SMEM7>>>(sl, z, z, D, 0);
    }
}